// round 4
// baseline (speedup 1.0000x reference)
#include <cuda_runtime.h>
#include <math.h>

// Problem constants
#define NBATCH 4
#define NID    16
#define NPAIR  (NBATCH*NID)
#define DD     32
#define HH     192
#define WW     192
#define DHW    (DD*HH*WW)          // 1179648
#define CHUNK  4096
#define NCHUNK (DHW/CHUNK)         // 288 exactly
#define NB     65536               // histogram bins over e in [0,2]
#define INV_W  32768.0f            // 1 / bin_width  (bin_width = 2/65536)

// ---------------- scratch (static device globals; no allocation) ----------------
__device__ unsigned g_negH[(size_t)NPAIR * NB];   // 16 MB
__device__ unsigned g_posH[(size_t)NPAIR * NB];   // 16 MB
__device__ float  g_acc[NPAIR][10];   // cnt, sx,sy,sz, ss0..2, sq0..2
__device__ float  g_bg[NBATCH];
__device__ float  g_center[NPAIR][3];
__device__ float  g_sexp[NPAIR][3];
__device__ float  g_var[NPAIR];
__device__ float  g_exists[NPAIR];
__device__ float  g_seedl[NPAIR];
__device__ double g_instl[NPAIR];

__device__ __forceinline__ float sigmoidf_(float x) {
    return 1.0f / (1.0f + __expf(-x));
}

// ---------------- K0: zero all accumulators / histograms ----------------
__global__ void k_zero() {
    const size_t n4 = (size_t)NPAIR * NB / 4;   // uint4 count per array
    uint4 z = make_uint4(0u, 0u, 0u, 0u);
    uint4* pn = reinterpret_cast<uint4*>(g_negH);
    uint4* pp = reinterpret_cast<uint4*>(g_posH);
    size_t stride = (size_t)gridDim.x * blockDim.x;
    for (size_t i = (size_t)blockIdx.x * blockDim.x + threadIdx.x; i < n4; i += stride) {
        pn[i] = z;
        pp[i] = z;
    }
    if (blockIdx.x == 0) {
        // FIX: NPAIR*10 = 640 > blockDim; must stride-loop, not single-shot guard.
        for (int t = threadIdx.x; t < NPAIR * 10; t += blockDim.x)
            g_acc[t / 10][t % 10] = 0.0f;
        for (int t = threadIdx.x; t < NBATCH; t += blockDim.x)
            g_bg[t] = 0.0f;
        for (int t = threadIdx.x; t < NPAIR; t += blockDim.x)
            g_seedl[t] = 0.0f;
    }
}

// ---------------- K1: per-(b,id) masked moments + background seed ----------------
__global__ void __launch_bounds__(256) k_stats(const float* __restrict__ pred,
                                               const int*   __restrict__ inst,
                                               const int*   __restrict__ labels,
                                               const float* __restrict__ xyzm) {
    __shared__ float acc[NID * 10];
    __shared__ float accbg;
    int b = blockIdx.y;
    for (int i = threadIdx.x; i < NID * 10; i += blockDim.x) acc[i] = 0.0f;
    if (threadIdx.x == 0) accbg = 0.0f;
    __syncthreads();

    const float* pb = pred + (size_t)b * 7 * DHW;
    const int*   ib = inst + (size_t)b * DHW;
    const int*   lb = labels + (size_t)b * DHW;
    int base = blockIdx.x * CHUNK;
    int lane = threadIdx.x & 31;

    #pragma unroll 4
    for (int k = 0; k < CHUNK / 256; k++) {
        int v = base + k * 256 + threadIdx.x;
        float s0 = pb[3 * DHW + v];
        float s1 = pb[4 * DHW + v];
        float s2 = pb[5 * DHW + v];
        float sd = pb[6 * DHW + v];
        float seed = sigmoidf_(sd);
        int   ii = ib[v];
        int   lv = lb[v];

        // background seed: warp reduce then one smem atomic
        float bgv = (lv == 0) ? seed * seed : 0.0f;
        #pragma unroll
        for (int off = 16; off > 0; off >>= 1)
            bgv += __shfl_down_sync(0xffffffffu, bgv, off);
        if (lane == 0 && bgv != 0.0f) atomicAdd(&accbg, bgv);

        if (ii >= 1) {
            int id = ii - 1;
            float x = xyzm[v];
            float y = xyzm[DHW + v];
            float z = xyzm[2 * DHW + v];
            float* a = &acc[id * 10];
            atomicAdd(a + 0, 1.0f);
            atomicAdd(a + 1, x);
            atomicAdd(a + 2, y);
            atomicAdd(a + 3, z);
            atomicAdd(a + 4, s0);
            atomicAdd(a + 5, s1);
            atomicAdd(a + 6, s2);
            atomicAdd(a + 7, s0 * s0);
            atomicAdd(a + 8, s1 * s1);
            atomicAdd(a + 9, s2 * s2);
        }
    }
    __syncthreads();
    for (int i = threadIdx.x; i < NID * 10; i += blockDim.x) {
        if (acc[i] != 0.0f) atomicAdd(&g_acc[b * NID + i / 10][i % 10], acc[i]);
    }
    if (threadIdx.x == 0 && accbg != 0.0f) atomicAdd(&g_bg[b], accbg);
}

// ---------------- K2: finalize per-pair stats ----------------
__global__ void k_finalize() {
    int p = threadIdx.x;
    if (p >= NPAIR) return;
    float cnt  = g_acc[p][0];
    float ex   = (cnt > 0.0f) ? 1.0f : 0.0f;
    float safe = fmaxf(cnt, 1.0f);
    float var  = 0.0f;
    #pragma unroll
    for (int k = 0; k < 3; k++) {
        float c  = g_acc[p][1 + k] / safe;
        float mu = g_acc[p][4 + k] / safe;
        var += g_acc[p][7 + k] - cnt * mu * mu;
        g_center[p][k] = c;
        g_sexp[p][k]   = __expf(10.0f * mu);
    }
    g_var[p]    = ex * (var / (3.0f * safe));
    g_exists[p] = ex;
}

// ---------------- K3: fused dist / seed-loss / error-histogram pass ----------------
__global__ void __launch_bounds__(256) k_dist(const float* __restrict__ pred,
                                              const int*   __restrict__ inst,
                                              const float* __restrict__ xyzm) {
    __shared__ float sc[NID][8];     // cx,cy,cz, e0,e1,e2, exists, pad
    __shared__ float sseed[NID];
    int b = blockIdx.y;
    if (threadIdx.x < NID * 7) {
        int id = threadIdx.x / 7, c = threadIdx.x % 7;
        float v;
        if (c < 3)      v = g_center[b * NID + id][c];
        else if (c < 6) v = g_sexp[b * NID + id][c - 3];
        else            v = g_exists[b * NID + id];
        sc[id][c] = v;
    }
    if (threadIdx.x < NID) sseed[threadIdx.x] = 0.0f;
    __syncthreads();

    const float* pb = pred + (size_t)b * 7 * DHW;
    const int*   ib = inst + (size_t)b * DHW;
    unsigned* negH = g_negH + (size_t)b * NID * NB;
    unsigned* posH = g_posH + (size_t)b * NID * NB;
    int base = blockIdx.x * CHUNK;

    for (int k = 0; k < CHUNK / 256; k++) {
        int v = base + k * 256 + threadIdx.x;
        float se0 = tanhf(pb[v])           + xyzm[v];
        float se1 = tanhf(pb[DHW + v])     + xyzm[DHW + v];
        float se2 = tanhf(pb[2 * DHW + v]) + xyzm[2 * DHW + v];
        float seed = sigmoidf_(pb[6 * DHW + v]);
        int   ii = ib[v];

        #pragma unroll
        for (int id = 0; id < NID; id++) {
            if (sc[id][6] == 0.0f) continue;
            float dx = se0 - sc[id][0];
            float dy = se1 - sc[id][1];
            float dz = se2 - sc[id][2];
            float t = fmaf(dx * dx, sc[id][3],
                      fmaf(dy * dy, sc[id][4],
                           dz * dz * sc[id][5]));
            float d = __expf(-t);
            bool pos = (ii == id + 1);
            float e = pos ? (2.0f - 2.0f * d) : (2.0f * d);
            int bin = (int)(e * INV_W);
            bin = min(bin, NB - 1);
            if (pos) {
                atomicAdd(&posH[id * NB + bin], 1u);
                float dv = seed - d;
                atomicAdd(&sseed[id], dv * dv);
            } else {
                atomicAdd(&negH[id * NB + bin], 1u);
            }
        }
    }
    __syncthreads();
    if (threadIdx.x < NID && sseed[threadIdx.x] != 0.0f)
        atomicAdd(&g_seedl[b * NID + threadIdx.x], sseed[threadIdx.x]);
}

// ---------------- K4: Lovasz via descending-bin scan (one block per pair) ----------------
__global__ void __launch_bounds__(256) k_lovasz() {
    int p = blockIdx.x;                         // 0..63
    __shared__ unsigned sp[256], sn[256];
    __shared__ unsigned op[257], on[257];
    __shared__ double  part[256];
    const unsigned* posH = g_posH + (size_t)p * NB;
    const unsigned* negH = g_negH + (size_t)p * NB;
    int t = threadIdx.x;
    const int CB = NB / 256;                    // 256 bins per thread

    // Phase 1: local sums over this thread's descending-e chunk
    unsigned lp = 0, ln = 0;
    for (int i = 0; i < CB; i++) {
        int bin = (NB - 1) - (t * CB + i);
        lp += posH[bin];
        ln += negH[bin];
    }
    sp[t] = lp; sn[t] = ln;
    __syncthreads();
    if (t == 0) {
        unsigned ap = 0, an = 0;
        for (int i = 0; i < 256; i++) { op[i] = ap; on[i] = an; ap += sp[i]; an += sn[i]; }
        op[256] = ap; on[256] = an;
    }
    __syncthreads();

    double contrib = 0.0;
    unsigned Pu = op[256];
    if (Pu > 0) {
        double P = (double)Pu;
        unsigned cp = op[t], cn = on[t];
        double Jprev = 1.0 - (P - (double)cp) / (P + (double)cn);  // = 0 when cp=cn=0
        for (int i = 0; i < CB; i++) {
            int bin = (NB - 1) - (t * CB + i);
            unsigned np = posH[bin], nn = negH[bin];
            if (np | nn) {
                cp += np; cn += nn;
                double J = 1.0 - (P - (double)cp) / (P + (double)cn);
                double eb = ((double)bin + 0.5) * (1.0 / 32768.0);
                contrib += eb * (J - Jprev);
                Jprev = J;
            }
        }
    }
    part[t] = contrib;
    __syncthreads();
    for (int s = 128; s > 0; s >>= 1) {
        if (t < s) part[t] += part[t + s];
        __syncthreads();
    }
    if (t == 0) g_instl[p] = part[0];
}

// ---------------- K5: assemble the 4 outputs ----------------
__global__ void k_final(float* __restrict__ out) {
    if (threadIdx.x != 0) return;
    double li = 0.0, lv = 0.0, ls = 0.0;
    for (int b = 0; b < NBATCH; b++) {
        double obj = 0.0, vv = 0.0, il = 0.0, sl = 0.0;
        for (int id = 0; id < NID; id++) {
            int p = b * NID + id;
            obj += (double)g_exists[p];
            vv  += (double)g_var[p];
            il  += g_instl[p];
            sl  += (double)g_seedl[p];
        }
        double denom = fmax(obj, 1.0);
        li += il / denom;
        lv += vv / denom;
        ls += (sl + (double)g_bg[b]) / (double)DHW;
    }
    li = li / NBATCH;                 // W_INST = 1
    lv = lv * 10.0 / NBATCH;          // W_VAR = 10
    ls = ls / NBATCH;                 // W_SEED = 1
    out[0] = (float)li;
    out[1] = (float)lv;
    out[2] = (float)ls;
    out[3] = (float)(li + lv + ls);
}

// ---------------- launch ----------------
extern "C" void kernel_launch(void* const* d_in, const int* in_sizes, int n_in,
                              void* d_out, int out_size) {
    const float* pred   = (const float*)d_in[0];   // (B,7,D,H,W)
    const int*   inst   = (const int*)d_in[1];     // (B,D,H,W)
    const int*   labels = (const int*)d_in[2];     // (B,D,H,W)
    // d_in[3] center_images — unused by the reference loss
    const float* xyzm   = (const float*)d_in[4];   // (3,D,H,W)
    float* out = (float*)d_out;

    k_zero<<<2048, 256>>>();
    dim3 g(NCHUNK, NBATCH);
    k_stats<<<g, 256>>>(pred, inst, labels, xyzm);
    k_finalize<<<1, 64>>>();
    k_dist<<<g, 256>>>(pred, inst, xyzm);
    k_lovasz<<<NPAIR, 256>>>();
    k_final<<<1, 32>>>(out);
}